// round 13
// baseline (speedup 1.0000x reference)
#include <cuda_runtime.h>
#include <cuda_fp16.h>
#include <cstdint>

#define E_DIM 256
#define D_DIM 128
#define MT    64           // tokens per CTA
#define NCH   16           // chunks (k16 each)

// fused smem: halves for q/k/v staging, floats for bias/prob
#define QSTR_H  136        // half row stride (272B, 16B-aligned, conflict-skewed)
#define H_Q     0
#define H_K     8704
#define H_V     17408      // ends 26112 halfs = 13056 floats
#define F_BI    13056      // 384 floats
#define F_PR    13440      // 512 floats
#define SMEM_FLOATS 13952  // 55,808 B -> 3 CTAs/SM

// pre_kernel smem: P 16384 + wq 256 + wk 256 = 16896 floats (67,584 B)
#define PRE_SMEM_FLOATS 16896

__device__ __half g_xh[16777216];      // x, fragment-major per 64-token tile (32MB)
__device__ __half g_Wh[3 * 65536];     // W, fragment-major
__device__ float  g_b[3 * E_DIM];

#define MMA_F16U(c, A, b0, b1) \
    asm volatile("mma.sync.aligned.m16n8k16.row.col.f32.f16.f16.f32 " \
        "{%0,%1,%2,%3}, {%4,%5,%6,%7}, {%8,%9}, {%0,%1,%2,%3};" \
        : "+f"((c)[0]), "+f"((c)[1]), "+f"((c)[2]), "+f"((c)[3]) \
        : "r"((A).x), "r"((A).y), "r"((A).z), "r"((A).w), "r"(b0), "r"(b1))

// ---- merged setup kernel (unchanged, validated) ----
__global__ __launch_bounds__(256)
void pre_kernel(const float* __restrict__ x,
                const float* __restrict__ Wq, const float* __restrict__ bq,
                const float* __restrict__ Wk, const float* __restrict__ bk,
                const float* __restrict__ Wv, const float* __restrict__ bv,
                const float* __restrict__ P) {
    extern __shared__ float s[];
    const int tid = threadIdx.x;

    if (blockIdx.x < 256) {
        const int e = blockIdx.x;
        float* ps  = s;
        float* wqs = s + 16384;
        float* wks = s + 16640;

        wqs[tid] = Wq[(size_t)tid * E_DIM + e];
        wks[tid] = Wk[(size_t)tid * E_DIM + e];
#pragma unroll
        for (int i = 0; i < 16; ++i)
            ((float4*)ps)[i * 256 + tid] = ((const float4*)P)[i * 256 + tid];
        __syncthreads();

        const int j = tid, h = j >> 7, jm = j & 127;
        const float* whq = wqs + h * D_DIM;
        const float* whk = wks + h * D_DIM;
        float aq0 = 0.f, aq1 = 0.f, ak0 = 0.f, ak1 = 0.f;
#pragma unroll 8
        for (int d = 0; d < D_DIM; d += 2) {
            float p0 = ps[d * D_DIM + jm];
            float p1 = ps[(d + 1) * D_DIM + jm];
            aq0 = fmaf(whq[d],     p0, aq0);
            aq1 = fmaf(whq[d + 1], p1, aq1);
            ak0 = fmaf(whk[d],     p0, ak0);
            ak1 = fmaf(whk[d + 1], p1, ak1);
        }
        float aq = aq0 + aq1, ak = ak0 + ak1;

        int k16 = e >> 4, reg = (e >> 3) & 1, halfidx = e & 1;
        int lane = ((jm & 7) << 2) | ((e & 7) >> 1);
        int wn = jm >> 5, nt = (jm >> 3) & 3, pair = nt >> 1, sub = nt & 1;
        size_t inner = (size_t)k16 * 2048 + wn * 512 + pair * 256
                     + lane * 8 + sub * 4 + reg * 2 + halfidx;
        g_Wh[(size_t)(0 * 2 + h) * 32768 + inner] = __float2half(aq);
        g_Wh[(size_t)(1 * 2 + h) * 32768 + inner] = __float2half(ak);
        g_Wh[(size_t)(2 * 2 + h) * 32768 + inner] = __float2half(Wv[(size_t)j * E_DIM + e]);

        if (e == 0) {
            float bqe = 0.f, bke = 0.f;
#pragma unroll 8
            for (int d = 0; d < D_DIM; ++d) {
                float p = ps[d * D_DIM + jm];
                bqe = fmaf(bq[h * D_DIM + d], p, bqe);
                bke = fmaf(bk[h * D_DIM + d], p, bke);
            }
            g_b[0 * E_DIM + j] = bqe;
            g_b[1 * E_DIM + j] = bke;
            g_b[2 * E_DIM + j] = bv[j];
        }
    } else {
        const int tile = blockIdx.x - 256;
        uint32_t* sh = (uint32_t*)s;
        const float4* xg4 = (const float4*)(x + (size_t)tile * MT * E_DIM);
#pragma unroll
        for (int i = 0; i < 16; ++i) {
            int idx = i * 256 + tid;
            int m = idx >> 6, k = (idx & 63) << 2;
            float4 v = xg4[idx];
            int row = m & 15, mtile = m >> 4, k16 = k >> 4;
#pragma unroll
            for (int jj = 0; jj < 2; ++jj) {
                int kk = k + 2 * jj;
                int lane = ((row & 7) << 2) | ((kk & 7) >> 1);
                int reg  = ((row >> 3) & 1) | (((kk >> 3) & 1) << 1);
                __half2 hv = jj ? __floats2half2_rn(v.z, v.w) : __floats2half2_rn(v.x, v.y);
                sh[((k16 * 4 + mtile) * 32 + lane) * 4 + reg] = *(uint32_t*)&hv;
            }
        }
        __syncthreads();
        uint4* go = (uint4*)(g_xh + (size_t)tile * 16384);
        const uint4* si = (const uint4*)sh;
#pragma unroll
        for (int i = 0; i < 8; ++i) go[i * 256 + tid] = si[i * 256 + tid];
    }
}

// CTA = 64 tokens x 1 head, 3 CTAs/SM. Three sequential register-pipelined
// barrier-free passes (q,k,v; acc=32 regs each), fragments LDG direct from
// fragment-major gmem. q/k/v staged fp16. Then in-CTA block attention.
__global__ __launch_bounds__(256, 3)
void fused_kernel(float* __restrict__ out) {
    extern __shared__ float sm[];
    __half* smh = (__half*)sm;
    const int tid  = threadIdx.x;
    const int w    = tid >> 5, lane = tid & 31;
    const int wm   = w >> 2, wn = w & 3;          // warp grid 2x4 over [64,128]
    const int tile = blockIdx.x >> 1, head = blockIdx.x & 1;

    // per-warp fragment bases (f4 units)
    const uint4* xq = (const uint4*)(g_xh + (size_t)tile * 16384)
                      + (uint32_t)(2 * wm * 32 + lane);
    const uint4* wbase = (const uint4*)(g_Wh + (size_t)head * 32768)
                         + (uint32_t)(wn * 64 + lane);

    // stage bias
    for (int i = tid; i < 384; i += 256)
        sm[F_BI + i] = g_b[(i >> 7) * E_DIM + head * D_DIM + (i & 127)];
    __syncthreads();

#pragma unroll 1
    for (int p = 0; p < 3; ++p) {
        const uint4* wq = wbase + (uint32_t)p * 8192;

        float acc[2][4][4];
#pragma unroll
        for (int mi = 0; mi < 2; ++mi)
#pragma unroll
            for (int ni = 0; ni < 4; ++ni) {
                int col = wn * 32 + ni * 8 + 2 * (lane & 3);
                float b0 = sm[F_BI + p * 128 + col], b1 = sm[F_BI + p * 128 + col + 1];
                acc[mi][ni][0] = b0; acc[mi][ni][1] = b1;
                acc[mi][ni][2] = b0; acc[mi][ni][3] = b1;
            }

        // software-pipelined chunk loop (1 chunk lookahead, no barriers)
        uint4 A0 = __ldg(xq),      A1 = __ldg(xq + 32);
        uint4 B0 = __ldg(wq),      B1 = __ldg(wq + 32);
#pragma unroll
        for (int c = 0; c < NCH; ++c) {
            uint4 A0n, A1n, B0n, B1n;
            if (c + 1 < NCH) {
                A0n = __ldg(xq + (c + 1) * 128);
                A1n = __ldg(xq + (c + 1) * 128 + 32);
                B0n = __ldg(wq + (c + 1) * 256);
                B1n = __ldg(wq + (c + 1) * 256 + 32);
            }
            MMA_F16U(acc[0][0], A0, B0.x, B0.y);
            MMA_F16U(acc[1][0], A1, B0.x, B0.y);
            MMA_F16U(acc[0][1], A0, B0.z, B0.w);
            MMA_F16U(acc[1][1], A1, B0.z, B0.w);
            MMA_F16U(acc[0][2], A0, B1.x, B1.y);
            MMA_F16U(acc[1][2], A1, B1.x, B1.y);
            MMA_F16U(acc[0][3], A0, B1.z, B1.w);
            MMA_F16U(acc[1][3], A1, B1.z, B1.w);
            A0 = A0n; A1 = A1n; B0 = B0n; B1 = B1n;
        }

        // stage this projection as fp16 (no barrier needed: own-warp region)
        __half* stg = smh + (p == 0 ? H_Q : (p == 1 ? H_K : H_V));
#pragma unroll
        for (int mi = 0; mi < 2; ++mi) {
            int row = wm * 32 + mi * 16 + (lane >> 2);
#pragma unroll
            for (int ni = 0; ni < 4; ++ni) {
                int col = wn * 32 + ni * 8 + 2 * (lane & 3);
                *(__half2*)(stg + row * QSTR_H + col) =
                    __floats2half2_rn(acc[mi][ni][0], acc[mi][ni][1]);
                *(__half2*)(stg + (row + 8) * QSTR_H + col) =
                    __floats2half2_rn(acc[mi][ni][2], acc[mi][ni][3]);
            }
        }
    }
    __syncthreads();

    // ---- block-diagonal attention: warp w -> block w (fp16 staged) ----
    const float scl = 0.08838834764831845f;   // 1/sqrt(128)
    {
        int blk = w;
        int i0 = lane >> 3, j0 = lane & 7;
        const uint4* q0r = (const uint4*)(smh + H_Q + (8 * blk + i0) * QSTR_H);
        const uint4* q1r = (const uint4*)(smh + H_Q + (8 * blk + i0 + 4) * QSTR_H);
        const uint4* k0r = (const uint4*)(smh + H_K + (8 * blk + j0) * QSTR_H);
        float s0 = 0.f, s1 = 0.f;
#pragma unroll
        for (int t = 0; t < 16; ++t) {
            uint4 qa = q0r[t], qb = q1r[t], kk = k0r[t];
            const __half2* ha = (const __half2*)&qa;
            const __half2* hb = (const __half2*)&qb;
            const __half2* hk = (const __half2*)&kk;
#pragma unroll
            for (int u = 0; u < 4; ++u) {
                float2 fk = __half22float2(hk[u]);
                float2 fa = __half22float2(ha[u]);
                float2 fb = __half22float2(hb[u]);
                s0 = fmaf(fa.x, fk.x, fmaf(fa.y, fk.y, s0));
                s1 = fmaf(fb.x, fk.x, fmaf(fb.y, fk.y, s1));
            }
        }
        s0 *= scl; s1 *= scl;
        float m0 = s0, m1 = s1;
#pragma unroll
        for (int off = 1; off < 8; off <<= 1) {
            m0 = fmaxf(m0, __shfl_xor_sync(0xffffffffu, m0, off));
            m1 = fmaxf(m1, __shfl_xor_sync(0xffffffffu, m1, off));
        }
        float e0 = __expf(s0 - m0), e1 = __expf(s1 - m1);
        float d0 = e0, d1 = e1;
#pragma unroll
        for (int off = 1; off < 8; off <<= 1) {
            d0 += __shfl_xor_sync(0xffffffffu, d0, off);
            d1 += __shfl_xor_sync(0xffffffffu, d1, off);
        }
        sm[F_PR + blk * 64 + lane]      = e0 / d0;
        sm[F_PR + blk * 64 + 32 + lane] = e1 / d1;
        __syncwarp();

        const float* prob = sm + F_PR + blk * 64;
        float4 o[8];
#pragma unroll
        for (int i = 0; i < 8; ++i) o[i] = make_float4(0.f, 0.f, 0.f, 0.f);
#pragma unroll
        for (int j = 0; j < 8; ++j) {
            const __half2* vr = (const __half2*)(smh + H_V + (8 * blk + j) * QSTR_H + lane * 4);
            float2 v01 = __half22float2(vr[0]);
            float2 v23 = __half22float2(vr[1]);
#pragma unroll
            for (int i = 0; i < 8; ++i) {
                float a = prob[i * 8 + j];
                o[i].x = fmaf(a, v01.x, o[i].x);
                o[i].y = fmaf(a, v01.y, o[i].y);
                o[i].z = fmaf(a, v23.x, o[i].z);
                o[i].w = fmaf(a, v23.y, o[i].w);
            }
        }
#pragma unroll
        for (int i = 0; i < 8; ++i) {
            size_t token = (size_t)tile * MT + 8 * blk + i;
            *(float4*)(out + token * E_DIM + head * D_DIM + lane * 4) = o[i];
        }
    }
}

extern "C" void kernel_launch(void* const* d_in, const int* in_sizes, int n_in,
                              void* d_out, int out_size) {
    const float* x  = (const float*)d_in[0];
    const float* Wq = (const float*)d_in[1];
    const float* bq = (const float*)d_in[2];
    const float* Wk = (const float*)d_in[3];
    const float* bk = (const float*)d_in[4];
    const float* Wv = (const float*)d_in[5];
    const float* bv = (const float*)d_in[6];
    const float* P  = (const float*)d_in[7];
    float* out = (float*)d_out;

    const int tokens = in_sizes[0] / E_DIM;      // B*N
    const int tiles  = tokens / MT;              // 1024
    const size_t pre_smem = (size_t)PRE_SMEM_FLOATS * sizeof(float);   // 67,584 B
    const size_t smem     = (size_t)SMEM_FLOATS * sizeof(float);       // 55,808 B

    cudaFuncSetAttribute(pre_kernel,
                         cudaFuncAttributeMaxDynamicSharedMemorySize, (int)pre_smem);
    cudaFuncSetAttribute(fused_kernel,
                         cudaFuncAttributeMaxDynamicSharedMemorySize, (int)smem);

    pre_kernel<<<256 + tiles, 256, pre_smem>>>(x, Wq, bq, Wk, bk, Wv, bv, P);
    fused_kernel<<<tiles * 2, 256, smem>>>(out);
}

// round 14
// speedup vs baseline: 1.0771x; 1.0771x over previous
#include <cuda_runtime.h>
#include <cuda_fp16.h>
#include <cstdint>

#define E_DIM 256
#define D_DIM 128
#define MT    64           // tokens per CTA
#define NCH   16           // chunks (k16 each)

// fused smem (floats): fp32 q/k/v staging + prob + bias (round-11 layout)
#define QSTR    132
#define F_Q     0
#define F_K     8448
#define F_V     16896
#define F_PR    25344
#define F_BI    25856
#define SMEM_FLOATS 26240          // 104,960 B -> 2 CTAs/SM

// pre_kernel smem: P 16384 + wq 256 + wk 256 = 16896 floats (67,584 B)
#define PRE_SMEM_FLOATS 16896

__device__ __half g_xh[16777216];      // x, fragment-major per 64-token tile (32MB)
__device__ __half g_Wh[3 * 65536];     // W, fragment-major
__device__ float  g_b[3 * E_DIM];

#define MMA_F16U(c, A, b0, b1) \
    asm volatile("mma.sync.aligned.m16n8k16.row.col.f32.f16.f16.f32 " \
        "{%0,%1,%2,%3}, {%4,%5,%6,%7}, {%8,%9}, {%0,%1,%2,%3};" \
        : "+f"((c)[0]), "+f"((c)[1]), "+f"((c)[2]), "+f"((c)[3]) \
        : "r"((A).x), "r"((A).y), "r"((A).z), "r"((A).w), "r"(b0), "r"(b1))

// ---- merged setup kernel (unchanged, validated) ----
__global__ __launch_bounds__(256)
void pre_kernel(const float* __restrict__ x,
                const float* __restrict__ Wq, const float* __restrict__ bq,
                const float* __restrict__ Wk, const float* __restrict__ bk,
                const float* __restrict__ Wv, const float* __restrict__ bv,
                const float* __restrict__ P) {
    extern __shared__ float s[];
    const int tid = threadIdx.x;

    if (blockIdx.x < 256) {
        const int e = blockIdx.x;
        float* ps  = s;
        float* wqs = s + 16384;
        float* wks = s + 16640;

        wqs[tid] = Wq[(size_t)tid * E_DIM + e];
        wks[tid] = Wk[(size_t)tid * E_DIM + e];
#pragma unroll
        for (int i = 0; i < 16; ++i)
            ((float4*)ps)[i * 256 + tid] = ((const float4*)P)[i * 256 + tid];
        __syncthreads();

        const int j = tid, h = j >> 7, jm = j & 127;
        const float* whq = wqs + h * D_DIM;
        const float* whk = wks + h * D_DIM;
        float aq0 = 0.f, aq1 = 0.f, ak0 = 0.f, ak1 = 0.f;
#pragma unroll 8
        for (int d = 0; d < D_DIM; d += 2) {
            float p0 = ps[d * D_DIM + jm];
            float p1 = ps[(d + 1) * D_DIM + jm];
            aq0 = fmaf(whq[d],     p0, aq0);
            aq1 = fmaf(whq[d + 1], p1, aq1);
            ak0 = fmaf(whk[d],     p0, ak0);
            ak1 = fmaf(whk[d + 1], p1, ak1);
        }
        float aq = aq0 + aq1, ak = ak0 + ak1;

        int k16 = e >> 4, reg = (e >> 3) & 1, halfidx = e & 1;
        int lane = ((jm & 7) << 2) | ((e & 7) >> 1);
        int wn = jm >> 5, nt = (jm >> 3) & 3, pair = nt >> 1, sub = nt & 1;
        size_t inner = (size_t)k16 * 2048 + wn * 512 + pair * 256
                     + lane * 8 + sub * 4 + reg * 2 + halfidx;
        g_Wh[(size_t)(0 * 2 + h) * 32768 + inner] = __float2half(aq);
        g_Wh[(size_t)(1 * 2 + h) * 32768 + inner] = __float2half(ak);
        g_Wh[(size_t)(2 * 2 + h) * 32768 + inner] = __float2half(Wv[(size_t)j * E_DIM + e]);

        if (e == 0) {
            float bqe = 0.f, bke = 0.f;
#pragma unroll 8
            for (int d = 0; d < D_DIM; ++d) {
                float p = ps[d * D_DIM + jm];
                bqe = fmaf(bq[h * D_DIM + d], p, bqe);
                bke = fmaf(bk[h * D_DIM + d], p, bke);
            }
            g_b[0 * E_DIM + j] = bqe;
            g_b[1 * E_DIM + j] = bke;
            g_b[2 * E_DIM + j] = bv[j];
        }
    } else {
        const int tile = blockIdx.x - 256;
        uint32_t* sh = (uint32_t*)s;
        const float4* xg4 = (const float4*)(x + (size_t)tile * MT * E_DIM);
#pragma unroll
        for (int i = 0; i < 16; ++i) {
            int idx = i * 256 + tid;
            int m = idx >> 6, k = (idx & 63) << 2;
            float4 v = xg4[idx];
            int row = m & 15, mtile = m >> 4, k16 = k >> 4;
#pragma unroll
            for (int jj = 0; jj < 2; ++jj) {
                int kk = k + 2 * jj;
                int lane = ((row & 7) << 2) | ((kk & 7) >> 1);
                int reg  = ((row >> 3) & 1) | (((kk >> 3) & 1) << 1);
                __half2 hv = jj ? __floats2half2_rn(v.z, v.w) : __floats2half2_rn(v.x, v.y);
                sh[((k16 * 4 + mtile) * 32 + lane) * 4 + reg] = *(uint32_t*)&hv;
            }
        }
        __syncthreads();
        uint4* go = (uint4*)(g_xh + (size_t)tile * 16384);
        const uint4* si = (const uint4*)sh;
#pragma unroll
        for (int i = 0; i < 8; ++i) go[i * 256 + tid] = si[i * 256 + tid];
    }
}

// CTA = 64 tokens x 1 head, 2 CTAs/SM. Two register-pipelined barrier-free
// passes: A = {q,k} (acc 64), B = {v} (acc 32). Fragments LDG direct from
// fragment-major gmem. fp32 staging; single barrier before attention.
__global__ __launch_bounds__(256, 2)
void fused_kernel(float* __restrict__ out) {
    extern __shared__ float sm[];
    const int tid  = threadIdx.x;
    const int w    = tid >> 5, lane = tid & 31;
    const int wm   = w >> 2, wn = w & 3;          // warp grid 2x4 over [64,128]
    const int tile = blockIdx.x >> 1, head = blockIdx.x & 1;

    // per-warp fragment bases (f4 units)
    const uint4* xq = (const uint4*)(g_xh + (size_t)tile * 16384)
                      + (uint32_t)(2 * wm * 32 + lane);
    const uint4* wbase = (const uint4*)(g_Wh + (size_t)head * 32768)
                         + (uint32_t)(wn * 64 + lane);

    // stage bias
    for (int i = tid; i < 384; i += 256)
        sm[F_BI + i] = g_b[(i >> 7) * E_DIM + head * D_DIM + (i & 127)];
    __syncthreads();

    const int colb = wn * 32 + 2 * (lane & 3);
    const int rowb = wm * 32 + (lane >> 2);

    // ================= pass A: q and k =================
    {
        const uint4* wq = wbase;                   // p=0
        const uint4* wk = wbase + 8192;            // p=1
        float aq[2][4][4], ak[2][4][4];
#pragma unroll
        for (int mi = 0; mi < 2; ++mi)
#pragma unroll
            for (int ni = 0; ni < 4; ++ni) {
                float q0 = sm[F_BI + colb + ni * 8], q1 = sm[F_BI + colb + ni * 8 + 1];
                float k0 = sm[F_BI + 128 + colb + ni * 8], k1 = sm[F_BI + 128 + colb + ni * 8 + 1];
                aq[mi][ni][0] = q0; aq[mi][ni][1] = q1; aq[mi][ni][2] = q0; aq[mi][ni][3] = q1;
                ak[mi][ni][0] = k0; ak[mi][ni][1] = k1; ak[mi][ni][2] = k0; ak[mi][ni][3] = k1;
            }

        uint4 A0 = __ldg(xq),      A1 = __ldg(xq + 32);
        uint4 Q0 = __ldg(wq),      Q1 = __ldg(wq + 32);
        uint4 K0 = __ldg(wk),      K1 = __ldg(wk + 32);
#pragma unroll
        for (int c = 0; c < NCH; ++c) {
            uint4 A0n, A1n, Q0n, Q1n, K0n, K1n;
            if (c + 1 < NCH) {
                A0n = __ldg(xq + (c + 1) * 128);
                A1n = __ldg(xq + (c + 1) * 128 + 32);
                Q0n = __ldg(wq + (c + 1) * 256);
                Q1n = __ldg(wq + (c + 1) * 256 + 32);
                K0n = __ldg(wk + (c + 1) * 256);
                K1n = __ldg(wk + (c + 1) * 256 + 32);
            }
            MMA_F16U(aq[0][0], A0, Q0.x, Q0.y);
            MMA_F16U(aq[1][0], A1, Q0.x, Q0.y);
            MMA_F16U(aq[0][1], A0, Q0.z, Q0.w);
            MMA_F16U(aq[1][1], A1, Q0.z, Q0.w);
            MMA_F16U(aq[0][2], A0, Q1.x, Q1.y);
            MMA_F16U(aq[1][2], A1, Q1.x, Q1.y);
            MMA_F16U(aq[0][3], A0, Q1.z, Q1.w);
            MMA_F16U(aq[1][3], A1, Q1.z, Q1.w);
            MMA_F16U(ak[0][0], A0, K0.x, K0.y);
            MMA_F16U(ak[1][0], A1, K0.x, K0.y);
            MMA_F16U(ak[0][1], A0, K0.z, K0.w);
            MMA_F16U(ak[1][1], A1, K0.z, K0.w);
            MMA_F16U(ak[0][2], A0, K1.x, K1.y);
            MMA_F16U(ak[1][2], A1, K1.x, K1.y);
            MMA_F16U(ak[0][3], A0, K1.z, K1.w);
            MMA_F16U(ak[1][3], A1, K1.z, K1.w);
            A0 = A0n; A1 = A1n; Q0 = Q0n; Q1 = Q1n; K0 = K0n; K1 = K1n;
        }

        // stage q, k (own-warp regions; no barrier needed yet)
#pragma unroll
        for (int mi = 0; mi < 2; ++mi) {
            int row = rowb + mi * 16;
#pragma unroll
            for (int ni = 0; ni < 4; ++ni) {
                int col = colb + ni * 8;
                sm[F_Q + row * QSTR + col]           = aq[mi][ni][0];
                sm[F_Q + row * QSTR + col + 1]       = aq[mi][ni][1];
                sm[F_Q + (row + 8) * QSTR + col]     = aq[mi][ni][2];
                sm[F_Q + (row + 8) * QSTR + col + 1] = aq[mi][ni][3];
                sm[F_K + row * QSTR + col]           = ak[mi][ni][0];
                sm[F_K + row * QSTR + col + 1]       = ak[mi][ni][1];
                sm[F_K + (row + 8) * QSTR + col]     = ak[mi][ni][2];
                sm[F_K + (row + 8) * QSTR + col + 1] = ak[mi][ni][3];
            }
        }
    }

    // ================= pass B: v =================
    {
        const uint4* wv = wbase + 16384;           // p=2
        float av[2][4][4];
#pragma unroll
        for (int mi = 0; mi < 2; ++mi)
#pragma unroll
            for (int ni = 0; ni < 4; ++ni) {
                float v0 = sm[F_BI + 256 + colb + ni * 8], v1 = sm[F_BI + 256 + colb + ni * 8 + 1];
                av[mi][ni][0] = v0; av[mi][ni][1] = v1; av[mi][ni][2] = v0; av[mi][ni][3] = v1;
            }

        uint4 A0 = __ldg(xq),      A1 = __ldg(xq + 32);
        uint4 V0 = __ldg(wv),      V1 = __ldg(wv + 32);
#pragma unroll
        for (int c = 0; c < NCH; ++c) {
            uint4 A0n, A1n, V0n, V1n;
            if (c + 1 < NCH) {
                A0n = __ldg(xq + (c + 1) * 128);
                A1n = __ldg(xq + (c + 1) * 128 + 32);
                V0n = __ldg(wv + (c + 1) * 256);
                V1n = __ldg(wv + (c + 1) * 256 + 32);
            }
            MMA_F16U(av[0][0], A0, V0.x, V0.y);
            MMA_F16U(av[1][0], A1, V0.x, V0.y);
            MMA_F16U(av[0][1], A0, V0.z, V0.w);
            MMA_F16U(av[1][1], A1, V0.z, V0.w);
            MMA_F16U(av[0][2], A0, V1.x, V1.y);
            MMA_F16U(av[1][2], A1, V1.x, V1.y);
            MMA_F16U(av[0][3], A0, V1.z, V1.w);
            MMA_F16U(av[1][3], A1, V1.z, V1.w);
            A0 = A0n; A1 = A1n; V0 = V0n; V1 = V1n;
        }

#pragma unroll
        for (int mi = 0; mi < 2; ++mi) {
            int row = rowb + mi * 16;
#pragma unroll
            for (int ni = 0; ni < 4; ++ni) {
                int col = colb + ni * 8;
                sm[F_V + row * QSTR + col]           = av[mi][ni][0];
                sm[F_V + row * QSTR + col + 1]       = av[mi][ni][1];
                sm[F_V + (row + 8) * QSTR + col]     = av[mi][ni][2];
                sm[F_V + (row + 8) * QSTR + col + 1] = av[mi][ni][3];
            }
        }
    }
    __syncthreads();   // single barrier: all staging visible

    // ---- block-diagonal attention: warp w -> block w ----
    float* qs = sm + F_Q; float* ks = sm + F_K; float* vs = sm + F_V;
    const float scl = 0.08838834764831845f;   // 1/sqrt(128)
    {
        int blk = w;
        int i0 = lane >> 3, j0 = lane & 7;
        const float4* q0 = (const float4*)(qs + (8 * blk + i0) * QSTR);
        const float4* q1 = (const float4*)(qs + (8 * blk + i0 + 4) * QSTR);
        const float4* k0 = (const float4*)(ks + (8 * blk + j0) * QSTR);
        float s0 = 0.f, s1 = 0.f;
#pragma unroll
        for (int t = 0; t < 32; ++t) {
            float4 kk = k0[t];
            float4 aa = q0[t];
            s0 += aa.x * kk.x + aa.y * kk.y + aa.z * kk.z + aa.w * kk.w;
            float4 cc = q1[t];
            s1 += cc.x * kk.x + cc.y * kk.y + cc.z * kk.z + cc.w * kk.w;
        }
        s0 *= scl; s1 *= scl;
        float m0 = s0, m1 = s1;
#pragma unroll
        for (int off = 1; off < 8; off <<= 1) {
            m0 = fmaxf(m0, __shfl_xor_sync(0xffffffffu, m0, off));
            m1 = fmaxf(m1, __shfl_xor_sync(0xffffffffu, m1, off));
        }
        float e0 = __expf(s0 - m0), e1 = __expf(s1 - m1);
        float d0 = e0, d1 = e1;
#pragma unroll
        for (int off = 1; off < 8; off <<= 1) {
            d0 += __shfl_xor_sync(0xffffffffu, d0, off);
            d1 += __shfl_xor_sync(0xffffffffu, d1, off);
        }
        sm[F_PR + blk * 64 + lane]      = e0 / d0;
        sm[F_PR + blk * 64 + 32 + lane] = e1 / d1;
        __syncwarp();

        const float* prob = sm + F_PR + blk * 64;
        float4 o[8];
#pragma unroll
        for (int i = 0; i < 8; ++i) o[i] = make_float4(0.f, 0.f, 0.f, 0.f);
#pragma unroll
        for (int j = 0; j < 8; ++j) {
            float4 v4 = *(const float4*)(vs + (8 * blk + j) * QSTR + lane * 4);
#pragma unroll
            for (int i = 0; i < 8; ++i) {
                float a = prob[i * 8 + j];
                o[i].x = fmaf(a, v4.x, o[i].x);
                o[i].y = fmaf(a, v4.y, o[i].y);
                o[i].z = fmaf(a, v4.z, o[i].z);
                o[i].w = fmaf(a, v4.w, o[i].w);
            }
        }
#pragma unroll
        for (int i = 0; i < 8; ++i) {
            size_t token = (size_t)tile * MT + 8 * blk + i;
            *(float4*)(out + token * E_DIM + head * D_DIM + lane * 4) = o[i];
        }
    }
}

extern "C" void kernel_launch(void* const* d_in, const int* in_sizes, int n_in,
                              void* d_out, int out_size) {
    const float* x  = (const float*)d_in[0];
    const float* Wq = (const float*)d_in[1];
    const float* bq = (const float*)d_in[2];
    const float* Wk = (const float*)d_in[3];
    const float* bk = (const float*)d_in[4];
    const float* Wv = (const float*)d_in[5];
    const float* bv = (const float*)d_in[6];
    const float* P  = (const float*)d_in[7];
    float* out = (float*)d_out;

    const int tokens = in_sizes[0] / E_DIM;      // B*N
    const int tiles  = tokens / MT;              // 1024
    const size_t pre_smem = (size_t)PRE_SMEM_FLOATS * sizeof(float);   // 67,584 B
    const size_t smem     = (size_t)SMEM_FLOATS * sizeof(float);       // 104,960 B

    cudaFuncSetAttribute(pre_kernel,
                         cudaFuncAttributeMaxDynamicSharedMemorySize, (int)pre_smem);
    cudaFuncSetAttribute(fused_kernel,
                         cudaFuncAttributeMaxDynamicSharedMemorySize, (int)smem);

    pre_kernel<<<256 + tiles, 256, pre_smem>>>(x, Wq, bq, Wk, bk, Wv, bv, P);
    fused_kernel<<<tiles * 2, 256, smem>>>(out);
}

// round 15
// speedup vs baseline: 1.5433x; 1.4328x over previous
#include <cuda_runtime.h>
#include <cuda_fp16.h>
#include <cstdint>

#define E_DIM 256
#define D_DIM 128
#define MT    64           // tokens per CTA
#define NCH   16           // chunks (k16 each)
#define NSTG  3
#define XROW  20           // x stage row stride (floats): 80B, 16B-aligned
#define STG_FL 1280        // floats per x stage (64 rows * 20)
#define STG_BY 5120u

// attention-phase smem (floats); x stages (3*5120B = 15KB) alias F_Q region
#define QSTR    132
#define F_Q     0
#define F_K     8448
#define F_V     16896
#define F_PR    25344
#define F_BI    25856
#define SMEM_FLOATS 26240          // 104,960 B -> 2 CTAs/SM

// prep smem: P 16384 + wq 256 + wk 256 = 16896 floats (67,584 B)
#define PRE_SMEM_FLOATS 16896

__device__ __half g_Wh[3 * 65536];     // W, fragment-major
__device__ float  g_b[3 * E_DIM];

__device__ __forceinline__ uint32_t h2u(__half2 h) { return *(uint32_t*)&h; }

#define MMA_F16(c, a, b0, b1) \
    asm volatile("mma.sync.aligned.m16n8k16.row.col.f32.f16.f16.f32 " \
        "{%0,%1,%2,%3}, {%4,%5,%6,%7}, {%8,%9}, {%0,%1,%2,%3};" \
        : "+f"((c)[0]), "+f"((c)[1]), "+f"((c)[2]), "+f"((c)[3]) \
        : "r"((a)[0]), "r"((a)[1]), "r"((a)[2]), "r"((a)[3]), "r"(b0), "r"(b1))

#define CP_ASYNC16(dst, src) \
    asm volatile("cp.async.ca.shared.global [%0], [%1], 16;" :: "r"(dst), "l"(src))
#define CP_COMMIT()  asm volatile("cp.async.commit_group;" ::: "memory")
#define CP_WAIT1()   asm volatile("cp.async.wait_group 1;" ::: "memory")
#define CP_WAIT0()   asm volatile("cp.async.wait_group 0;" ::: "memory")

// ---- prep: fold P into Wq/Wk, write W fp16 fragment-major (LDS dot) ----
__global__ __launch_bounds__(256)
void prep_kernel(const float* __restrict__ Wq, const float* __restrict__ bq,
                 const float* __restrict__ Wk, const float* __restrict__ bk,
                 const float* __restrict__ Wv, const float* __restrict__ bv,
                 const float* __restrict__ P) {
    extern __shared__ float s[];
    const int tid = threadIdx.x;
    const int e = blockIdx.x;
    float* ps  = s;
    float* wqs = s + 16384;
    float* wks = s + 16640;

    wqs[tid] = Wq[(size_t)tid * E_DIM + e];
    wks[tid] = Wk[(size_t)tid * E_DIM + e];
#pragma unroll
    for (int i = 0; i < 16; ++i)
        ((float4*)ps)[i * 256 + tid] = ((const float4*)P)[i * 256 + tid];
    __syncthreads();

    const int j = tid, h = j >> 7, jm = j & 127;
    const float* whq = wqs + h * D_DIM;
    const float* whk = wks + h * D_DIM;
    float aq0 = 0.f, aq1 = 0.f, ak0 = 0.f, ak1 = 0.f;
#pragma unroll 8
    for (int d = 0; d < D_DIM; d += 2) {
        float p0 = ps[d * D_DIM + jm];
        float p1 = ps[(d + 1) * D_DIM + jm];
        aq0 = fmaf(whq[d],     p0, aq0);
        aq1 = fmaf(whq[d + 1], p1, aq1);
        ak0 = fmaf(whk[d],     p0, ak0);
        ak1 = fmaf(whk[d + 1], p1, ak1);
    }
    float aq = aq0 + aq1, ak = ak0 + ak1;

    int k16 = e >> 4, reg = (e >> 3) & 1, halfidx = e & 1;
    int lane = ((jm & 7) << 2) | ((e & 7) >> 1);
    int wn = jm >> 5, nt = (jm >> 3) & 3, pair = nt >> 1, sub = nt & 1;
    size_t inner = (size_t)k16 * 2048 + wn * 512 + pair * 256
                 + lane * 8 + sub * 4 + reg * 2 + halfidx;
    g_Wh[(size_t)(0 * 2 + h) * 32768 + inner] = __float2half(aq);
    g_Wh[(size_t)(1 * 2 + h) * 32768 + inner] = __float2half(ak);
    g_Wh[(size_t)(2 * 2 + h) * 32768 + inner] = __float2half(Wv[(size_t)j * E_DIM + e]);

    if (e == 0) {
        float bqe = 0.f, bke = 0.f;
#pragma unroll 8
        for (int d = 0; d < D_DIM; ++d) {
            float p = ps[d * D_DIM + jm];
            bqe = fmaf(bq[h * D_DIM + d], p, bqe);
            bke = fmaf(bk[h * D_DIM + d], p, bke);
        }
        g_b[0 * E_DIM + j] = bqe;
        g_b[1 * E_DIM + j] = bke;
        g_b[2 * E_DIM + j] = bv[j];
    }
}

// CTA = 64 tokens x 1 head, 2 CTAs/SM. Merged qkv k-loop: x fp32 cp.async ring
// with in-kernel fp16 conversion of A fragments (same rounding prex applied);
// W (B fragments) __ldg direct from fragment-major g_Wh (L2-hot). Then in-CTA
// block-diagonal attention. No g_xh, no prex pass.
__global__ __launch_bounds__(256, 2)
void fused_kernel(const float* __restrict__ x, float* __restrict__ out) {
    extern __shared__ float sm[];
    const int tid  = threadIdx.x;
    const int w    = tid >> 5, lane = tid & 31;
    const int wm   = w >> 2, wn = w & 3;          // warp grid 2x4 over [64,128]
    const int tile = blockIdx.x >> 1, head = blockIdx.x & 1;

    uint32_t smb;
    asm("{\n\t.reg .u64 t;\n\tcvta.to.shared.u64 t, %1;\n\tcvt.u32.u64 %0, t;\n\t}"
        : "=r"(smb) : "l"(sm));

    const float* xg = x + (size_t)tile * MT * E_DIM;
    const uint4* wp = (const uint4*)(g_Wh + (size_t)head * 32768)
                      + (uint32_t)(wn * 64 + lane);

    const int xm = tid >> 2, xkq = tid & 3;
    const uint32_t xdst = (uint32_t)(xm * XROW + xkq * 4) * 4u;   // bytes
    const float* xsrc0 = xg + (size_t)xm * E_DIM + xkq * 4;

    auto issue = [&](int c) {
        uint32_t bb = smb + (uint32_t)(c % NSTG) * STG_BY;
        CP_ASYNC16(bb + xdst, xsrc0 + c * 16);
        CP_COMMIT();
    };

    for (int i = tid; i < 384; i += 256)
        sm[F_BI + i] = g_b[(i >> 7) * E_DIM + head * D_DIM + (i & 127)];

    issue(0); issue(1);
    __syncthreads();                               // bias visible

    float acc[3][2][4][4];
#pragma unroll
    for (int p = 0; p < 3; ++p)
#pragma unroll
        for (int mi = 0; mi < 2; ++mi)
#pragma unroll
            for (int ni = 0; ni < 4; ++ni) {
                int col = wn * 32 + ni * 8 + 2 * (lane & 3);
                float b0 = sm[F_BI + p * 128 + col], b1 = sm[F_BI + p * 128 + col + 1];
                acc[p][mi][ni][0] = b0; acc[p][mi][ni][1] = b1;
                acc[p][mi][ni][2] = b0; acc[p][mi][ni][3] = b1;
            }

    const int r0  = wm * 32 + (lane >> 2);
    const int kk0 = 2 * (lane & 3);

    for (int c = 0; c < NCH; ++c) {
        if (c < NCH - 1) { CP_WAIT1(); } else { CP_WAIT0(); }
        __syncthreads();                           // x chunk c visible
        const float* st = sm + (size_t)(c % NSTG) * STG_FL;

        uint32_t a0[4], a1[4];
        {
            const float* b0p = st + r0 * XROW + kk0;
            float2 f;
            f = *(const float2*)(b0p);                a0[0] = h2u(__floats2half2_rn(f.x, f.y));
            f = *(const float2*)(b0p + 8 * XROW);     a0[1] = h2u(__floats2half2_rn(f.x, f.y));
            f = *(const float2*)(b0p + 8);            a0[2] = h2u(__floats2half2_rn(f.x, f.y));
            f = *(const float2*)(b0p + 8 * XROW + 8); a0[3] = h2u(__floats2half2_rn(f.x, f.y));
            const float* b1p = b0p + 16 * XROW;
            f = *(const float2*)(b1p);                a1[0] = h2u(__floats2half2_rn(f.x, f.y));
            f = *(const float2*)(b1p + 8 * XROW);     a1[1] = h2u(__floats2half2_rn(f.x, f.y));
            f = *(const float2*)(b1p + 8);            a1[2] = h2u(__floats2half2_rn(f.x, f.y));
            f = *(const float2*)(b1p + 8 * XROW + 8); a1[3] = h2u(__floats2half2_rn(f.x, f.y));
        }

        uint4 b0 = __ldg(wp), b1 = __ldg(wp + 32);
        MMA_F16(acc[0][0][0], a0, b0.x, b0.y);
        MMA_F16(acc[0][1][0], a1, b0.x, b0.y);
        MMA_F16(acc[0][0][1], a0, b0.z, b0.w);
        MMA_F16(acc[0][1][1], a1, b0.z, b0.w);
        MMA_F16(acc[0][0][2], a0, b1.x, b1.y);
        MMA_F16(acc[0][1][2], a1, b1.x, b1.y);
        MMA_F16(acc[0][0][3], a0, b1.z, b1.w);
        MMA_F16(acc[0][1][3], a1, b1.z, b1.w);

        b0 = __ldg(wp + 8192); b1 = __ldg(wp + 8192 + 32);
        MMA_F16(acc[1][0][0], a0, b0.x, b0.y);
        MMA_F16(acc[1][1][0], a1, b0.x, b0.y);
        MMA_F16(acc[1][0][1], a0, b0.z, b0.w);
        MMA_F16(acc[1][1][1], a1, b0.z, b0.w);
        MMA_F16(acc[1][0][2], a0, b1.x, b1.y);
        MMA_F16(acc[1][1][2], a1, b1.x, b1.y);
        MMA_F16(acc[1][0][3], a0, b1.z, b1.w);
        MMA_F16(acc[1][1][3], a1, b1.z, b1.w);

        b0 = __ldg(wp + 16384); b1 = __ldg(wp + 16384 + 32);
        MMA_F16(acc[2][0][0], a0, b0.x, b0.y);
        MMA_F16(acc[2][1][0], a1, b0.x, b0.y);
        MMA_F16(acc[2][0][1], a0, b0.z, b0.w);
        MMA_F16(acc[2][1][1], a1, b0.z, b0.w);
        MMA_F16(acc[2][0][2], a0, b1.x, b1.y);
        MMA_F16(acc[2][1][2], a1, b1.x, b1.y);
        MMA_F16(acc[2][0][3], a0, b1.z, b1.w);
        MMA_F16(acc[2][1][3], a1, b1.z, b1.w);

        wp += 256;                                 // next k16 in W
        if (c + 2 < NCH) issue(c + 2);             // stage (c-1)%3 free
    }
    __syncthreads();                               // x stages dead; reuse smem

    // ---- stage q/k/v ----
#pragma unroll
    for (int p = 0; p < 3; ++p) {
        float* stg = sm + p * 8448;
#pragma unroll
        for (int mi = 0; mi < 2; ++mi) {
            int row = wm * 32 + mi * 16 + (lane >> 2);
#pragma unroll
            for (int ni = 0; ni < 4; ++ni) {
                int col = wn * 32 + ni * 8 + 2 * (lane & 3);
                stg[row * QSTR + col]           = acc[p][mi][ni][0];
                stg[row * QSTR + col + 1]       = acc[p][mi][ni][1];
                stg[(row + 8) * QSTR + col]     = acc[p][mi][ni][2];
                stg[(row + 8) * QSTR + col + 1] = acc[p][mi][ni][3];
            }
        }
    }
    __syncthreads();

    // ---- block-diagonal attention: warp w -> block w ----
    float* qs = sm + F_Q; float* ks = sm + F_K; float* vs = sm + F_V;
    const float scl = 0.08838834764831845f;   // 1/sqrt(128)
    {
        int blk = w;
        int i0 = lane >> 3, j0 = lane & 7;
        const float4* q0 = (const float4*)(qs + (8 * blk + i0) * QSTR);
        const float4* q1 = (const float4*)(qs + (8 * blk + i0 + 4) * QSTR);
        const float4* k0 = (const float4*)(ks + (8 * blk + j0) * QSTR);
        float s0 = 0.f, s1 = 0.f;
#pragma unroll
        for (int t = 0; t < 32; ++t) {
            float4 kk = k0[t];
            float4 aa = q0[t];
            s0 += aa.x * kk.x + aa.y * kk.y + aa.z * kk.z + aa.w * kk.w;
            float4 cc = q1[t];
            s1 += cc.x * kk.x + cc.y * kk.y + cc.z * kk.z + cc.w * kk.w;
        }
        s0 *= scl; s1 *= scl;
        float m0 = s0, m1 = s1;
#pragma unroll
        for (int off = 1; off < 8; off <<= 1) {
            m0 = fmaxf(m0, __shfl_xor_sync(0xffffffffu, m0, off));
            m1 = fmaxf(m1, __shfl_xor_sync(0xffffffffu, m1, off));
        }
        float e0 = __expf(s0 - m0), e1 = __expf(s1 - m1);
        float d0 = e0, d1 = e1;
#pragma unroll
        for (int off = 1; off < 8; off <<= 1) {
            d0 += __shfl_xor_sync(0xffffffffu, d0, off);
            d1 += __shfl_xor_sync(0xffffffffu, d1, off);
        }
        sm[F_PR + blk * 64 + lane]      = e0 / d0;
        sm[F_PR + blk * 64 + 32 + lane] = e1 / d1;
        __syncwarp();

        const float* prob = sm + F_PR + blk * 64;
        float4 o[8];
#pragma unroll
        for (int i = 0; i < 8; ++i) o[i] = make_float4(0.f, 0.f, 0.f, 0.f);
#pragma unroll
        for (int j = 0; j < 8; ++j) {
            float4 v4 = *(const float4*)(vs + (8 * blk + j) * QSTR + lane * 4);
#pragma unroll
            for (int i = 0; i < 8; ++i) {
                float a = prob[i * 8 + j];
                o[i].x = fmaf(a, v4.x, o[i].x);
                o[i].y = fmaf(a, v4.y, o[i].y);
                o[i].z = fmaf(a, v4.z, o[i].z);
                o[i].w = fmaf(a, v4.w, o[i].w);
            }
        }
#pragma unroll
        for (int i = 0; i < 8; ++i) {
            size_t token = (size_t)tile * MT + 8 * blk + i;
            *(float4*)(out + token * E_DIM + head * D_DIM + lane * 4) = o[i];
        }
    }
}

extern "C" void kernel_launch(void* const* d_in, const int* in_sizes, int n_in,
                              void* d_out, int out_size) {
    const float* x  = (const float*)d_in[0];
    const float* Wq = (const float*)d_in[1];
    const float* bq = (const float*)d_in[2];
    const float* Wk = (const float*)d_in[3];
    const float* bk = (const float*)d_in[4];
    const float* Wv = (const float*)d_in[5];
    const float* bv = (const float*)d_in[6];
    const float* P  = (const float*)d_in[7];
    float* out = (float*)d_out;

    const int tokens = in_sizes[0] / E_DIM;      // B*N
    const int tiles  = tokens / MT;              // 1024
    const size_t pre_smem = (size_t)PRE_SMEM_FLOATS * sizeof(float);   // 67,584 B
    const size_t smem     = (size_t)SMEM_FLOATS * sizeof(float);       // 104,960 B

    cudaFuncSetAttribute(prep_kernel,
                         cudaFuncAttributeMaxDynamicSharedMemorySize, (int)pre_smem);
    cudaFuncSetAttribute(fused_kernel,
                         cudaFuncAttributeMaxDynamicSharedMemorySize, (int)smem);

    prep_kernel<<<256, 256, pre_smem>>>(Wq, bq, Wk, bk, Wv, bv, P);
    fused_kernel<<<tiles * 2, 256, smem>>>(x, out);
}

// round 17
// speedup vs baseline: 1.8245x; 1.1822x over previous
#include <cuda_runtime.h>
#include <cuda_fp16.h>
#include <cstdint>

#define E_DIM 256
#define D_DIM 128
#define MT    64           // tokens per CTA
#define NCH   16           // chunks (k16 each)
#define NSTG  3
#define STG_BY 2048u       // x stage bytes (1024 halfs)

// attention-phase smem (floats); x stages (3*2048B = 6KB) alias F_Q region
#define QSTR    132
#define F_Q     0
#define F_K     8448
#define F_V     16896
#define F_PR    25344
#define F_BI    25856
#define SMEM_FLOATS 26240          // 104,960 B -> 2 CTAs/SM

// pre_kernel smem: P half 8192 + wq 256 + wk 256 = 8704 floats (34,816 B)
#define PRE_SMEM_FLOATS 8704

__device__ __half g_xh[16777216];      // x, fragment-major per 64-token tile (32MB)
__device__ __half g_Wh[3 * 65536];     // W, fragment-major
__device__ float  g_b[3 * E_DIM];

#define MMA_F16(c, a, b0, b1) \
    asm volatile("mma.sync.aligned.m16n8k16.row.col.f32.f16.f16.f32 " \
        "{%0,%1,%2,%3}, {%4,%5,%6,%7}, {%8,%9}, {%0,%1,%2,%3};" \
        : "+f"((c)[0]), "+f"((c)[1]), "+f"((c)[2]), "+f"((c)[3]) \
        : "r"((a)[0]), "r"((a)[1]), "r"((a)[2]), "r"((a)[3]), "r"(b0), "r"(b1))

#define CP_ASYNC16(dst, src) \
    asm volatile("cp.async.ca.shared.global [%0], [%1], 16;" :: "r"(dst), "l"(src))
#define CP_COMMIT()  asm volatile("cp.async.commit_group;" ::: "memory")
#define CP_WAIT1()   asm volatile("cp.async.wait_group 1;" ::: "memory")
#define CP_WAIT0()   asm volatile("cp.async.wait_group 0;" ::: "memory")

// ---- merged setup kernel ----
// blocks [0,256):   prep — fold P into Wq/Wk, W -> fp16 fragment-major.
//                   P staged in TWO 32KB halves so merged smem is 34.8KB
//                   (prex blocks get 6 CTAs/SM instead of 3).
// blocks [256,1280): prex — x -> fp16 fragment-major tiles (validated).
__global__ __launch_bounds__(256)
void pre_kernel(const float* __restrict__ x,
                const float* __restrict__ Wq, const float* __restrict__ bq,
                const float* __restrict__ Wk, const float* __restrict__ bk,
                const float* __restrict__ Wv, const float* __restrict__ bv,
                const float* __restrict__ P) {
    extern __shared__ float s[];
    const int tid = threadIdx.x;

    if (blockIdx.x < 256) {
        // ================= prep (two-phase P staging) =================
        const int e = blockIdx.x;
        float* ps  = s;                           // P rows half: [64][128]
        float* wqs = s + 8192;                    // Wq column e (256)
        float* wks = s + 8448;                    // Wk column e

        wqs[tid] = Wq[(size_t)tid * E_DIM + e];
        wks[tid] = Wk[(size_t)tid * E_DIM + e];

        const int j = tid, h = j >> 7, jm = j & 127;
        float aq0 = 0.f, aq1 = 0.f, ak0 = 0.f, ak1 = 0.f;
        float bqe = 0.f, bke = 0.f;

        for (int half = 0; half < 2; ++half) {
            __syncthreads();                      // prior phase reads done
#pragma unroll
            for (int i = 0; i < 8; ++i)
                ((float4*)ps)[i * 256 + tid] =
                    ((const float4*)P)[half * 2048 + i * 256 + tid];
            __syncthreads();

            const float* whq = wqs + h * D_DIM + half * 64;
            const float* whk = wks + h * D_DIM + half * 64;
#pragma unroll 8
            for (int d = 0; d < 64; d += 2) {
                float p0 = ps[d * D_DIM + jm];
                float p1 = ps[(d + 1) * D_DIM + jm];
                aq0 = fmaf(whq[d],     p0, aq0);
                aq1 = fmaf(whq[d + 1], p1, aq1);
                ak0 = fmaf(whk[d],     p0, ak0);
                ak1 = fmaf(whk[d + 1], p1, ak1);
            }
            if (e == 0) {
#pragma unroll 8
                for (int d = 0; d < 64; ++d) {
                    float p = ps[d * D_DIM + jm];
                    bqe = fmaf(bq[h * D_DIM + half * 64 + d], p, bqe);
                    bke = fmaf(bk[h * D_DIM + half * 64 + d], p, bke);
                }
            }
        }
        float aq = aq0 + aq1, ak = ak0 + ak1;

        // fragment-major store (validated layout)
        int k16 = e >> 4, reg = (e >> 3) & 1, halfidx = e & 1;
        int lane = ((jm & 7) << 2) | ((e & 7) >> 1);
        int wn = jm >> 5, nt = (jm >> 3) & 3, pair = nt >> 1, sub = nt & 1;
        size_t inner = (size_t)k16 * 2048 + wn * 512 + pair * 256
                     + lane * 8 + sub * 4 + reg * 2 + halfidx;
        g_Wh[(size_t)(0 * 2 + h) * 32768 + inner] = __float2half(aq);
        g_Wh[(size_t)(1 * 2 + h) * 32768 + inner] = __float2half(ak);
        g_Wh[(size_t)(2 * 2 + h) * 32768 + inner] = __float2half(Wv[(size_t)j * E_DIM + e]);

        if (e == 0) {
            g_b[0 * E_DIM + j] = bqe;
            g_b[1 * E_DIM + j] = bke;
            g_b[2 * E_DIM + j] = bv[j];
        }
    } else {
        // ================= prex (unchanged, validated) =================
        const int tile = blockIdx.x - 256;
        uint32_t* sh = (uint32_t*)s;              // 32KB
        const float4* xg4 = (const float4*)(x + (size_t)tile * MT * E_DIM);
#pragma unroll
        for (int i = 0; i < 16; ++i) {
            int idx = i * 256 + tid;
            int m = idx >> 6, k = (idx & 63) << 2;
            float4 v = xg4[idx];
            int row = m & 15, mtile = m >> 4, k16 = k >> 4;
#pragma unroll
            for (int jj = 0; jj < 2; ++jj) {
                int kk = k + 2 * jj;
                int lane = ((row & 7) << 2) | ((kk & 7) >> 1);
                int reg  = ((row >> 3) & 1) | (((kk >> 3) & 1) << 1);
                __half2 hv = jj ? __floats2half2_rn(v.z, v.w) : __floats2half2_rn(v.x, v.y);
                sh[((k16 * 4 + mtile) * 32 + lane) * 4 + reg] = *(uint32_t*)&hv;
            }
        }
        __syncthreads();
        uint4* go = (uint4*)(g_xh + (size_t)tile * 16384);
        const uint4* si = (const uint4*)sh;
#pragma unroll
        for (int i = 0; i < 8; ++i) go[i * 256 + tid] = si[i * 256 + tid];
    }
}

// CTA = 64 tokens x 1 head, 2 CTAs/SM. Merged qkv k-loop: x fp16 cp.async
// ring (with per-chunk barrier — the sound version, round 11 verbatim);
// W (B fragments) __ldg direct from fragment-major g_Wh (L2-hot). Then
// in-CTA block-diagonal attention.
__global__ __launch_bounds__(256, 2)
void fused_kernel(float* __restrict__ out) {
    extern __shared__ float sm[];
    const int tid  = threadIdx.x;
    const int w    = tid >> 5, lane = tid & 31;
    const int wm   = w >> 2, wn = w & 3;          // warp grid 2x4 over [64,128]
    const int tile = blockIdx.x >> 1, head = blockIdx.x & 1;

    uint32_t smb;
    asm("{\n\t.reg .u64 t;\n\tcvta.to.shared.u64 t, %1;\n\tcvt.u32.u64 %0, t;\n\t}"
        : "=r"(smb) : "l"(sm));

    const __half* xsrc = g_xh + (size_t)tile * 16384;
    const uint4* wp = (const uint4*)(g_Wh + (size_t)head * 32768)
                      + (uint32_t)(wn * 64 + lane);

    auto issue = [&](int c) {
        uint32_t bb = smb + (uint32_t)(c % NSTG) * STG_BY;
        if (tid < 128)
            CP_ASYNC16(bb + (uint32_t)tid * 16u, xsrc + (size_t)c * 1024 + tid * 8);
        CP_COMMIT();
    };

    // stage bias
    for (int i = tid; i < 384; i += 256)
        sm[F_BI + i] = g_b[(i >> 7) * E_DIM + head * D_DIM + (i & 127)];

    issue(0); issue(1);
    __syncthreads();                               // bias visible

    float acc[3][2][4][4];
#pragma unroll
    for (int p = 0; p < 3; ++p)
#pragma unroll
        for (int mi = 0; mi < 2; ++mi)
#pragma unroll
            for (int ni = 0; ni < 4; ++ni) {
                int col = wn * 32 + ni * 8 + 2 * (lane & 3);
                float b0 = sm[F_BI + p * 128 + col], b1 = sm[F_BI + p * 128 + col + 1];
                acc[p][mi][ni][0] = b0; acc[p][mi][ni][1] = b1;
                acc[p][mi][ni][2] = b0; acc[p][mi][ni][3] = b1;
            }

    for (int c = 0; c < NCH; ++c) {
        // B fragments straight from L2 (W hot: 384KB reused by all CTAs)
        uint4 B0 = __ldg(wp);             uint4 B1 = __ldg(wp + 32);
        uint4 B2 = __ldg(wp + 8192);      uint4 B3 = __ldg(wp + 8192 + 32);
        uint4 B4 = __ldg(wp + 16384);     uint4 B5 = __ldg(wp + 16384 + 32);

        if (c < NCH - 1) { CP_WAIT1(); } else { CP_WAIT0(); }
        __syncthreads();                           // x chunk c visible
        const uint4* st = (const uint4*)((const char*)sm + (size_t)(c % NSTG) * STG_BY);

        uint32_t a[2][4];
        *(uint4*)a[0] = st[(2 * wm + 0) * 32 + lane];
        *(uint4*)a[1] = st[(2 * wm + 1) * 32 + lane];

        MMA_F16(acc[0][0][0], a[0], B0.x, B0.y);
        MMA_F16(acc[0][1][0], a[1], B0.x, B0.y);
        MMA_F16(acc[0][0][1], a[0], B0.z, B0.w);
        MMA_F16(acc[0][1][1], a[1], B0.z, B0.w);
        MMA_F16(acc[0][0][2], a[0], B1.x, B1.y);
        MMA_F16(acc[0][1][2], a[1], B1.x, B1.y);
        MMA_F16(acc[0][0][3], a[0], B1.z, B1.w);
        MMA_F16(acc[0][1][3], a[1], B1.z, B1.w);

        MMA_F16(acc[1][0][0], a[0], B2.x, B2.y);
        MMA_F16(acc[1][1][0], a[1], B2.x, B2.y);
        MMA_F16(acc[1][0][1], a[0], B2.z, B2.w);
        MMA_F16(acc[1][1][1], a[1], B2.z, B2.w);
        MMA_F16(acc[1][0][2], a[0], B3.x, B3.y);
        MMA_F16(acc[1][1][2], a[1], B3.x, B3.y);
        MMA_F16(acc[1][0][3], a[0], B3.z, B3.w);
        MMA_F16(acc[1][1][3], a[1], B3.z, B3.w);

        MMA_F16(acc[2][0][0], a[0], B4.x, B4.y);
        MMA_F16(acc[2][1][0], a[1], B4.x, B4.y);
        MMA_F16(acc[2][0][1], a[0], B4.z, B4.w);
        MMA_F16(acc[2][1][1], a[1], B4.z, B4.w);
        MMA_F16(acc[2][0][2], a[0], B5.x, B5.y);
        MMA_F16(acc[2][1][2], a[1], B5.x, B5.y);
        MMA_F16(acc[2][0][3], a[0], B5.z, B5.w);
        MMA_F16(acc[2][1][3], a[1], B5.z, B5.w);

        wp += 256;                                 // next k16
        if (c + 2 < NCH) issue(c + 2);             // x buf (c-1)%3 free
    }
    __syncthreads();

    // ---- stage q/k/v (GEMM stages now dead) ----
#pragma unroll
    for (int p = 0; p < 3; ++p) {
        float* stg = sm + p * 8448;
#pragma unroll
        for (int mi = 0; mi < 2; ++mi) {
            int row = wm * 32 + mi * 16 + (lane >> 2);
#pragma unroll
            for (int ni = 0; ni < 4; ++ni) {
                int col = wn * 32 + ni * 8 + 2 * (lane & 3);
                stg[row * QSTR + col]           = acc[p][mi][ni][0];
                stg[row * QSTR + col + 1]       = acc[p][mi][ni][1];
                stg[(row + 8) * QSTR + col]     = acc[p][mi][ni][2];
                stg[(row + 8) * QSTR + col + 1] = acc[p][mi][ni][3];
            }
        }
    }
    __syncthreads();

    // ---- block-diagonal attention: warp w -> block w ----
    float* qs = sm + F_Q; float* ks = sm + F_K; float* vs = sm + F_V;
    const float scl = 0.08838834764831845f;   // 1/sqrt(128)
    {
        int blk = w;
        int i0 = lane >> 3, j0 = lane & 7;
        const float4* q0 = (const float4*)(qs + (8 * blk + i0) * QSTR);
        const float4* q1 = (const float4*)(qs + (8 * blk + i0 + 4) * QSTR);
        const float4* k0 = (const float4*)(ks + (8 * blk + j0) * QSTR);
        float s0 = 0.f, s1 = 0.f;
#pragma unroll
        for (int t = 0; t < 32; ++t) {
            float4 kk = k0[t];
            float4 aa = q0[t];
            s0 += aa.x * kk.x + aa.y * kk.y + aa.z * kk.z + aa.w * kk.w;
            float4 cc = q1[t];
            s1 += cc.x * kk.x + cc.y * kk.y + cc.z * kk.z + cc.w * kk.w;
        }
        s0 *= scl; s1 *= scl;
        float m0 = s0, m1 = s1;
#pragma unroll
        for (int off = 1; off < 8; off <<= 1) {
            m0 = fmaxf(m0, __shfl_xor_sync(0xffffffffu, m0, off));
            m1 = fmaxf(m1, __shfl_xor_sync(0xffffffffu, m1, off));
        }
        float e0 = __expf(s0 - m0), e1 = __expf(s1 - m1);
        float d0 = e0, d1 = e1;
#pragma unroll
        for (int off = 1; off < 8; off <<= 1) {
            d0 += __shfl_xor_sync(0xffffffffu, d0, off);
            d1 += __shfl_xor_sync(0xffffffffu, d1, off);
        }
        sm[F_PR + blk * 64 + lane]      = e0 / d0;
        sm[F_PR + blk * 64 + 32 + lane] = e1 / d1;
        __syncwarp();

        const float* prob = sm + F_PR + blk * 64;
        float4 o[8];
#pragma unroll
        for (int i = 0; i < 8; ++i) o[i] = make_float4(0.f, 0.f, 0.f, 0.f);
#pragma unroll
        for (int j = 0; j < 8; ++j) {
            float4 v4 = *(const float4*)(vs + (8 * blk + j) * QSTR + lane * 4);
#pragma unroll
            for (int i = 0; i < 8; ++i) {
                float a = prob[i * 8 + j];
                o[i].x = fmaf(a, v4.x, o[i].x);
                o[i].y = fmaf(a, v4.y, o[i].y);
                o[i].z = fmaf(a, v4.z, o[i].z);
                o[i].w = fmaf(a, v4.w, o[i].w);
            }
        }
#pragma unroll
        for (int i = 0; i < 8; ++i) {
            size_t token = (size_t)tile * MT + 8 * blk + i;
            *(float4*)(out + token * E_DIM + head * D_DIM + lane * 4) = o[i];
        }
    }
}

extern "C" void kernel_launch(void* const* d_in, const int* in_sizes, int n_in,
                              void* d_out, int out_size) {
    const float* x  = (const float*)d_in[0];
    const float* Wq = (const float*)d_in[1];
    const float* bq = (const float*)d_in[2];
    const float* Wk = (const float*)d_in[3];
    const float* bk = (const float*)d_in[4];
    const float* Wv = (const float*)d_in[5];
    const float* bv = (const float*)d_in[6];
    const float* P  = (const float*)d_in[7];
    float* out = (float*)d_out;

    const int tokens = in_sizes[0] / E_DIM;      // B*N
    const int tiles  = tokens / MT;              // 1024
    const size_t pre_smem = (size_t)PRE_SMEM_FLOATS * sizeof(float);   // 34,816 B
    const size_t smem     = (size_t)SMEM_FLOATS * sizeof(float);       // 104,960 B

    cudaFuncSetAttribute(pre_kernel,
                         cudaFuncAttributeMaxDynamicSharedMemorySize, (int)pre_smem);
    cudaFuncSetAttribute(fused_kernel,
                         cudaFuncAttributeMaxDynamicSharedMemorySize, (int)smem);

    pre_kernel<<<256 + tiles, 256, pre_smem>>>(x, Wq, bq, Wk, bk, Wv, bv, P);
    fused_kernel<<<tiles * 2, 256, smem>>>(out);
}